// round 15
// baseline (speedup 1.0000x reference)
#include <cuda_runtime.h>
#include <cuda_fp16.h>
#include <cuda_bf16.h>

// Inputs (metadata order): data [E*3 f32], t0, tn, beta [1 f32], z0 [N*2 f32]
// Output: scalar f32 = -(sum(log_int) - sum(exp(log_int)))
//
// Math: li = beta - d,  d = |z_i - z_j|^2
//   sum(li)      = E*beta - sum(d)
//   sum(exp(li)) = exp(beta) * sum(exp(-d))
// exp(-d) = 2^(-d*log2e) via MUFU ex2.approx.
//
// R15: the 12 MB event stream is moved by the TMA bulk engine (cp.async.bulk
// -> smem double buffer, 24 KB / 2048-event chunks), not warp LDGs: the
// stream no longer depends on warp scoreboard MLP. Events are consumed from
// smem as float2 (2 events/thread/chunk, no shuffles). z0 table as half2
// (40 KB). 2 persistent blocks/SM. Champion atomicAdd+ticket tail.

#define CHUNK_EV    2048
#define CHUNK_BYTES (CHUNK_EV * 12)          // 24576, 16B multiple

__device__ float g_partial[2];        // [0]=sum(d), [1]=sum(exp(-d)); zero-init
__device__ unsigned int g_ticket;     // wraps via atomicInc -> replay-safe

__device__ __forceinline__ float exp_negd(float d) {
    float x = d * -1.4426950408889634f;
    float r;
    asm("ex2.approx.ftz.f32 %0, %1;" : "=f"(r) : "f"(x));
    return r;
}

__device__ __forceinline__ unsigned h2_bits(__half2 h) {
    unsigned u;
    memcpy(&u, &h, 4);
    return u;
}

__device__ __forceinline__ void acc_pair(const __half2* __restrict__ tab,
                                         float fi, float fj,
                                         float& s_d, float& s_e)
{
    int i = __float2int_rz(fi);
    int j = __float2int_rz(fj);
    float2 zi = __half22float2(tab[i]);
    float2 zj = __half22float2(tab[j]);
    float dx = zi.x - zj.x, dy = zi.y - zj.y;
    float d = fmaf(dx, dx, dy * dy);
    s_d += d;
    s_e += exp_negd(d);
}

__device__ __forceinline__ void mbar_wait(unsigned mbar, unsigned parity) {
    asm volatile(
        "{\n\t"
        ".reg .pred p;\n\t"
        "W_%=: mbarrier.try_wait.parity.acquire.cta.shared::cta.b64 p, [%0], %1, 0x989680;\n\t"
        "@p bra D_%=;\n\t"
        "bra W_%=;\n\t"
        "D_%=:\n\t"
        "}"
        :: "r"(mbar), "r"(parity) : "memory");
}

__global__ void __launch_bounds__(1024, 2)
nll_kernel(const float* __restrict__ data,
           const float* __restrict__ beta,
           const float* __restrict__ z0,
           float* __restrict__ out,
           int E, int N, int tab_bytes)
{
    extern __shared__ __align__(16) char smem[];
    __half2* tab = (__half2*)smem;                     // N half2
    char* buf0 = smem + tab_bytes;                     // CHUNK_BYTES
    char* buf1 = buf0 + CHUNK_BYTES;                   // CHUNK_BYTES
    // 2 mbarriers after buffers
    unsigned smem_u32;
    asm("{ .reg .u64 t; cvta.to.shared.u64 t, %1; cvt.u32.u64 %0, t; }"
        : "=r"(smem_u32) : "l"((void*)smem));
    const unsigned mb0 = smem_u32 + tab_bytes + 2 * CHUNK_BYTES;
    const unsigned mb1 = mb0 + 8;

    const int tid = threadIdx.x;
    const int nchunk = E / CHUNK_EV;

    // ---- init mbarriers ----
    if (tid == 0) {
        asm volatile("mbarrier.init.shared.b64 [%0], 1;" :: "r"(mb0) : "memory");
        asm volatile("mbarrier.init.shared.b64 [%0], 1;" :: "r"(mb1) : "memory");
    }
    __syncthreads();

    // ---- issue first two TMA chunk loads (engine runs during table fill) ----
    const int c0 = blockIdx.x;
    const int c1 = blockIdx.x + gridDim.x;
    if (tid == 0) {
        if (c0 < nchunk) {
            asm volatile("mbarrier.arrive.expect_tx.shared.b64 _, [%0], %1;"
                         :: "r"(mb0), "r"((unsigned)CHUNK_BYTES) : "memory");
            asm volatile("cp.async.bulk.shared::cta.global.mbarrier::complete_tx::bytes"
                         " [%0], [%1], %2, [%3];"
                         :: "r"(smem_u32 + (unsigned)tab_bytes),
                            "l"((const char*)data + (size_t)c0 * CHUNK_BYTES),
                            "r"((unsigned)CHUNK_BYTES), "r"(mb0) : "memory");
        }
        if (c1 < nchunk) {
            asm volatile("mbarrier.arrive.expect_tx.shared.b64 _, [%0], %1;"
                         :: "r"(mb1), "r"((unsigned)CHUNK_BYTES) : "memory");
            asm volatile("cp.async.bulk.shared::cta.global.mbarrier::complete_tx::bytes"
                         " [%0], [%1], %2, [%3];"
                         :: "r"(smem_u32 + (unsigned)tab_bytes + CHUNK_BYTES),
                            "l"((const char*)data + (size_t)c1 * CHUNK_BYTES),
                            "r"((unsigned)CHUNK_BYTES), "r"(mb1) : "memory");
        }
    }

    // ---- fill z0 table as half2 (overlaps TMA flights) ----
    {
        const float4* z4 = (const float4*)z0;
        int npair = N >> 1;
        for (int k = tid; k < npair; k += blockDim.x) {
            float4 v = z4[k];
            __half2 h0 = __floats2half2_rn(v.x, v.y);
            __half2 h1 = __floats2half2_rn(v.z, v.w);
            *reinterpret_cast<uint2*>(&tab[2 * k]) =
                make_uint2(h2_bits(h0), h2_bits(h1));
        }
        if ((N & 1) && tid == 0) {
            float2 v = ((const float2*)z0)[N - 1];
            tab[N - 1] = __floats2half2_rn(v.x, v.y);
        }
    }
    __syncthreads();

    float s_d = 0.0f;
    float s_e = 0.0f;

    // ---- pipelined chunk loop ----
    int phase0 = 0, phase1 = 0;
    int buf = 0;
    for (int c = c0; c < nchunk; c += gridDim.x) {
        const unsigned mb   = buf ? mb1 : mb0;
        const char* bptr    = buf ? buf1 : buf0;
        int& phase          = buf ? phase1 : phase0;

        mbar_wait(mb, (unsigned)phase);
        phase ^= 1;

        // 2048 events, 1024 threads: thread t handles events 2t, 2t+1
        // floats f[6t..6t+5]: (i0,j0,t0,i1,j1,t1)
        const float2* b2 = (const float2*)bptr;
        float2 p0 = b2[3 * tid + 0];
        float2 p1 = b2[3 * tid + 1];
        float2 p2 = b2[3 * tid + 2];
        acc_pair(tab, p0.x, p0.y, s_d, s_e);
        acc_pair(tab, p1.y, p2.x, s_d, s_e);

        // all threads done reading this buffer before refill
        __syncthreads();

        int cnext = c + 2 * gridDim.x;
        if (cnext < nchunk && tid == 0) {
            asm volatile("mbarrier.arrive.expect_tx.shared.b64 _, [%0], %1;"
                         :: "r"(mb), "r"((unsigned)CHUNK_BYTES) : "memory");
            asm volatile("cp.async.bulk.shared::cta.global.mbarrier::complete_tx::bytes"
                         " [%0], [%1], %2, [%3];"
                         :: "r"(smem_u32 + (unsigned)tab_bytes + (buf ? CHUNK_BYTES : 0)),
                            "l"((const char*)data + (size_t)cnext * CHUNK_BYTES),
                            "r"((unsigned)CHUNK_BYTES), "r"(mb) : "memory");
        }
        buf ^= 1;
    }

    // ---- remainder events (E % CHUNK_EV), scalar global path ----
    {
        int rbase = nchunk * CHUNK_EV;
        int gtid = blockIdx.x * blockDim.x + threadIdx.x;
        int T = gridDim.x * blockDim.x;
        for (int e = rbase + gtid; e < E; e += T)
            acc_pair(tab, data[3 * e + 0], data[3 * e + 1], s_d, s_e);
    }

    // ---- warp reduction ----
    #pragma unroll
    for (int o = 16; o > 0; o >>= 1) {
        s_d += __shfl_xor_sync(0xffffffffu, s_d, o);
        s_e += __shfl_xor_sync(0xffffffffu, s_e, o);
    }

    // ---- block reduction ----
    __shared__ float sm_d[32];
    __shared__ float sm_e[32];
    const int lane = threadIdx.x & 31;
    const int warp = threadIdx.x >> 5;
    if (lane == 0) { sm_d[warp] = s_d; sm_e[warp] = s_e; }
    __syncthreads();

    if (warp == 0) {
        const int nwarps = blockDim.x >> 5;
        s_d = (lane < nwarps) ? sm_d[lane] : 0.0f;
        s_e = (lane < nwarps) ? sm_e[lane] : 0.0f;
        #pragma unroll
        for (int o = 16; o > 0; o >>= 1) {
            s_d += __shfl_xor_sync(0xffffffffu, s_d, o);
            s_e += __shfl_xor_sync(0xffffffffu, s_e, o);
        }
        if (lane == 0) {
            atomicAdd(&g_partial[0], s_d);
            atomicAdd(&g_partial[1], s_e);
            __threadfence();
            unsigned t = atomicInc(&g_ticket, gridDim.x - 1);  // wraps
            if (t == gridDim.x - 1) {
                float Sd = atomicExch(&g_partial[0], 0.0f);
                float Se = atomicExch(&g_partial[1], 0.0f);
                float b = beta[0];
                float sl = (float)E * b - Sd;       // sum(log intensities)
                float se = expf(b) * Se;            // sum(exp(log intensities))
                out[0] = se - sl;                   // -(sl - se)
            }
        }
    }
}

extern "C" void kernel_launch(void* const* d_in, const int* in_sizes, int n_in,
                              void* d_out, int out_size)
{
    const float* data = (const float*)d_in[0];
    // d_in[1] = t0, d_in[2] = tn  (unused)
    const float* beta = (const float*)d_in[3];
    const float* z0   = (const float*)d_in[4];
    float* out = (float*)d_out;

    const int E = in_sizes[0] / 3;
    const int N = in_sizes[4] / 2;

    const int tab_bytes = ((N * 4) + 15) & ~15;        // half2 table, 16B-aligned
    const size_t smem = (size_t)tab_bytes + 2 * CHUNK_BYTES + 16;  // + 2 mbars

    cudaFuncSetAttribute(nll_kernel,
                         cudaFuncAttributeMaxDynamicSharedMemorySize,
                         (int)smem);

    const int threads = 1024;
    int blocks = 296;                                  // 2 blocks/SM, one wave
    int max_blocks = (E + threads - 1) / threads;
    if (blocks > max_blocks) blocks = max_blocks;

    nll_kernel<<<blocks, threads, smem>>>(data, beta, z0, out, E, N, tab_bytes);
}

// round 16
// speedup vs baseline: 1.0299x; 1.0299x over previous
#include <cuda_runtime.h>
#include <cuda_fp16.h>
#include <cuda_bf16.h>

// Inputs (metadata order): data [E*3 f32], t0, tn, beta [1 f32], z0 [N*2 f32]
// Output: scalar f32 = -(sum(log_int) - sum(exp(log_int)))
//
// Math: li = beta - d,  d = |z_i - z_j|^2
//   sum(li)      = E*beta - sum(d)
//   sum(exp(li)) = exp(beta) * sum(exp(-d))
// exp(-d) = 2^(-d*log2e) via MUFU ex2.approx.
//
// FINAL (locked champion = R13 + 16B-STS fill):
//  - z0 table as half2 in smem (40 KB), 2 blocks/SM x 1024 thr (~76% occ)
//  - grid-stride quad loop, float4 event reads
//  - atomicAdd + wrapping-ticket tail (replay-deterministic)
// Measured family: kernel ~9.5us cold, wall ~10.7us (harness replay floor).

__device__ float g_partial[2];        // [0]=sum(d), [1]=sum(exp(-d)); zero-init
__device__ unsigned int g_ticket;     // wraps via atomicInc -> replay-safe

__device__ __forceinline__ float exp_negd(float d) {
    float x = d * -1.4426950408889634f;
    float r;
    asm("ex2.approx.ftz.f32 %0, %1;" : "=f"(r) : "f"(x));
    return r;
}

__device__ __forceinline__ unsigned h2_bits(__half2 h) {
    unsigned u;
    memcpy(&u, &h, 4);
    return u;
}

__global__ void __launch_bounds__(1024, 2)
nll_kernel(const float* __restrict__ data,
           const float* __restrict__ beta,
           const float* __restrict__ z0,
           float* __restrict__ out,
           int E, int N)
{
    extern __shared__ __half2 tab[];   // N half2 = 40 KB for N=10000

    // ---- stage z0 into smem as half2; 32B in -> 16B out per thread-iter ----
    {
        const float4* z4 = (const float4*)z0;
        int nqq = N >> 2;                          // groups of 4 points
        for (int k = threadIdx.x; k < nqq; k += blockDim.x) {
            float4 va = z4[2 * k + 0];             // points 4k, 4k+1
            float4 vb = z4[2 * k + 1];             // points 4k+2, 4k+3
            uint4 o;
            o.x = h2_bits(__floats2half2_rn(va.x, va.y));
            o.y = h2_bits(__floats2half2_rn(va.z, va.w));
            o.z = h2_bits(__floats2half2_rn(vb.x, vb.y));
            o.w = h2_bits(__floats2half2_rn(vb.z, vb.w));
            *reinterpret_cast<uint4*>(&tab[4 * k]) = o;
        }
        // remainder points (N % 4)
        for (int p = (nqq << 2) + threadIdx.x; p < N; p += blockDim.x) {
            float2 v = ((const float2*)z0)[p];
            tab[p] = __floats2half2_rn(v.x, v.y);
        }
    }
    __syncthreads();

    float s_d = 0.0f;   // sum of d
    float s_e = 0.0f;   // sum of exp(-d)

    const int T = gridDim.x * blockDim.x;
    const int gtid = blockIdx.x * blockDim.x + threadIdx.x;
    const int nquad = E >> 2;
    const float4* dp = (const float4*)data;   // 3 float4 per 4 events

    for (int q = gtid; q < nquad; q += T) {
        float4 a = dp[3 * q + 0];   // i0 j0 t0 i1
        float4 b = dp[3 * q + 1];   // j1 t1 i2 j2
        float4 c = dp[3 * q + 2];   // t2 i3 j3 t3

        int i0 = __float2int_rz(a.x), j0 = __float2int_rz(a.y);
        int i1 = __float2int_rz(a.w), j1 = __float2int_rz(b.x);
        int i2 = __float2int_rz(b.z), j2 = __float2int_rz(b.w);
        int i3 = __float2int_rz(c.y), j3 = __float2int_rz(c.z);

        float2 zi0 = __half22float2(tab[i0]), zj0 = __half22float2(tab[j0]);
        float2 zi1 = __half22float2(tab[i1]), zj1 = __half22float2(tab[j1]);
        float2 zi2 = __half22float2(tab[i2]), zj2 = __half22float2(tab[j2]);
        float2 zi3 = __half22float2(tab[i3]), zj3 = __half22float2(tab[j3]);

        float dx0 = zi0.x - zj0.x, dy0 = zi0.y - zj0.y;
        float dx1 = zi1.x - zj1.x, dy1 = zi1.y - zj1.y;
        float dx2 = zi2.x - zj2.x, dy2 = zi2.y - zj2.y;
        float dx3 = zi3.x - zj3.x, dy3 = zi3.y - zj3.y;

        float d0 = fmaf(dx0, dx0, dy0 * dy0);
        float d1 = fmaf(dx1, dx1, dy1 * dy1);
        float d2 = fmaf(dx2, dx2, dy2 * dy2);
        float d3 = fmaf(dx3, dx3, dy3 * dy3);

        s_d += (d0 + d1) + (d2 + d3);
        s_e += (exp_negd(d0) + exp_negd(d1)) + (exp_negd(d2) + exp_negd(d3));
    }

    // tail events (E % 4)
    {
        int rbase = nquad << 2;
        int r = E - rbase;
        if (gtid < r) {
            int e = rbase + gtid;
            int i = __float2int_rz(data[3 * e + 0]);
            int j = __float2int_rz(data[3 * e + 1]);
            float2 zi = __half22float2(tab[i]), zj = __half22float2(tab[j]);
            float dx = zi.x - zj.x, dy = zi.y - zj.y;
            float d = fmaf(dx, dx, dy * dy);
            s_d += d;
            s_e += exp_negd(d);
        }
    }

    // ---- warp reduction ----
    #pragma unroll
    for (int o = 16; o > 0; o >>= 1) {
        s_d += __shfl_xor_sync(0xffffffffu, s_d, o);
        s_e += __shfl_xor_sync(0xffffffffu, s_e, o);
    }

    // ---- block reduction ----
    __shared__ float sm_d[32];
    __shared__ float sm_e[32];
    const int lane = threadIdx.x & 31;
    const int warp = threadIdx.x >> 5;
    if (lane == 0) { sm_d[warp] = s_d; sm_e[warp] = s_e; }
    __syncthreads();

    if (warp == 0) {
        const int nwarps = blockDim.x >> 5;
        s_d = (lane < nwarps) ? sm_d[lane] : 0.0f;
        s_e = (lane < nwarps) ? sm_e[lane] : 0.0f;
        #pragma unroll
        for (int o = 16; o > 0; o >>= 1) {
            s_d += __shfl_xor_sync(0xffffffffu, s_d, o);
            s_e += __shfl_xor_sync(0xffffffffu, s_e, o);
        }
        if (lane == 0) {
            atomicAdd(&g_partial[0], s_d);
            atomicAdd(&g_partial[1], s_e);
            __threadfence();
            unsigned t = atomicInc(&g_ticket, gridDim.x - 1);  // wraps
            if (t == gridDim.x - 1) {
                float Sd = atomicExch(&g_partial[0], 0.0f);
                float Se = atomicExch(&g_partial[1], 0.0f);
                float b = beta[0];
                float sl = (float)E * b - Sd;       // sum(log intensities)
                float se = expf(b) * Se;            // sum(exp(log intensities))
                out[0] = se - sl;                   // -(sl - se)
            }
        }
    }
}

extern "C" void kernel_launch(void* const* d_in, const int* in_sizes, int n_in,
                              void* d_out, int out_size)
{
    const float* data = (const float*)d_in[0];
    // d_in[1] = t0, d_in[2] = tn  (unused)
    const float* beta = (const float*)d_in[3];
    const float* z0   = (const float*)d_in[4];
    float* out = (float*)d_out;

    const int E = in_sizes[0] / 3;
    const int N = in_sizes[4] / 2;
    const size_t smem = (size_t)N * sizeof(__half2);   // 40 KB for N=10000

    cudaFuncSetAttribute(nll_kernel,
                         cudaFuncAttributeMaxDynamicSharedMemorySize,
                         (int)smem);

    const int threads = 1024;
    int blocks = 296;                                  // 2 blocks/SM, one wave
    int max_blocks = (E + threads - 1) / threads;
    if (blocks > max_blocks) blocks = max_blocks;

    nll_kernel<<<blocks, threads, smem>>>(data, beta, z0, out, E, N);
}